// round 11
// baseline (speedup 1.0000x reference)
#include <cuda_runtime.h>
#include <cuda_fp16.h>
#include <cstdint>

// out[b,n,m,0]=cos(src_n,tgt_m), out[b,n,m,1]=1/(1+||src_n-tgt_m||)
// dot via 2-pass split-fp16 mma.sync: hiA*hiB + hiA*loB, fp32 accumulate.

#define NN 2048
#define CC 128
#define ROWSZ (4 * NN)

__device__ __half g_hiS[ROWSZ * CC];
__device__ __half g_hiT[ROWSZ * CC];
__device__ __half g_loT[ROWSZ * CC];
__device__ float2 g_nS[ROWSZ];   // {|s|^2, 1/max(|s|,eps)}
__device__ float2 g_nT[ROWSZ];

// ---------------------------------------------------------------------------
// prep: fp32 -> fp16 hi (+ lo for tgt only) + fused row norms. Warp per row.
// ---------------------------------------------------------------------------
__global__ void prep(const float* __restrict__ S, const float* __restrict__ T) {
    int gw = (blockIdx.x * blockDim.x + threadIdx.x) >> 5;
    int lane = threadIdx.x & 31;
    if (gw >= ROWSZ) return;
    bool ist = (blockIdx.y != 0);
    const float* p = (ist ? T : S) + (size_t)gw * CC + lane * 4;
    float4 v = *(const float4*)p;
    float sq = v.x * v.x + v.y * v.y + v.z * v.z + v.w * v.w;
#pragma unroll
    for (int o = 16; o; o >>= 1) sq += __shfl_xor_sync(0xffffffffu, sq, o);

    __half2 h01 = __floats2half2_rn(v.x, v.y);
    __half2 h23 = __floats2half2_rn(v.z, v.w);

    size_t off = (size_t)gw * CC + lane * 4;
    if (ist) {
        float2 f01 = __half22float2(h01);
        float2 f23 = __half22float2(h23);
        __half2 l01 = __floats2half2_rn(v.x - f01.x, v.y - f01.y);
        __half2 l23 = __floats2half2_rn(v.z - f23.x, v.w - f23.y);
        *(uint2*)(g_hiT + off) = make_uint2(*(uint32_t*)&h01, *(uint32_t*)&h23);
        *(uint2*)(g_loT + off) = make_uint2(*(uint32_t*)&l01, *(uint32_t*)&l23);
    } else {
        *(uint2*)(g_hiS + off) = make_uint2(*(uint32_t*)&h01, *(uint32_t*)&h23);
    }
    if (lane == 0) {
        float2 nv;
        nv.x = sq;
        nv.y = 1.0f / fmaxf(sqrtf(sq), 1e-12f);
        (ist ? g_nT : g_nS)[gw] = nv;
    }
}

// ---------------------------------------------------------------------------
__device__ __forceinline__ uint32_t s2u(const void* p) {
    uint32_t a;
    asm("{ .reg .u64 t; cvta.to.shared.u64 t, %1; cvt.u32.u64 %0, t; }" : "=r"(a) : "l"(p));
    return a;
}
// 128 rows x 32 halfs tile, 16B granules. slot = (row&7)^kg^((row&1)<<2):
// conflict-free for cp.async store phases and ldmatrix read phases.
__device__ __forceinline__ uint32_t toff(int row, int kg) {
    return (uint32_t)((kg << 11) + ((row >> 3) << 7) +
                      (((((row & 7) ^ kg) ^ ((row & 1) << 2))) << 4));
}
__device__ __forceinline__ void cpasync16(uint32_t s, const void* g) {
    asm volatile("cp.async.cg.shared.global [%0], [%1], 16;" :: "r"(s), "l"(g) : "memory");
}
template <int N>
__device__ __forceinline__ void cpwait() {
    asm volatile("cp.async.wait_group %0;" :: "n"(N) : "memory");
}
__device__ __forceinline__ void ldm4(uint32_t& r0, uint32_t& r1, uint32_t& r2,
                                     uint32_t& r3, uint32_t a) {
    asm volatile("ldmatrix.sync.aligned.m8n8.x4.shared.b16 {%0,%1,%2,%3}, [%4];"
                 : "=r"(r0), "=r"(r1), "=r"(r2), "=r"(r3) : "r"(a));
}
__device__ __forceinline__ void mma16816(float* c, const uint32_t* a, const uint32_t* b) {
    asm volatile(
        "mma.sync.aligned.m16n8k16.row.col.f32.f16.f16.f32 "
        "{%0,%1,%2,%3}, {%4,%5,%6,%7}, {%8,%9}, {%0,%1,%2,%3};"
        : "+f"(c[0]), "+f"(c[1]), "+f"(c[2]), "+f"(c[3])
        : "r"(a[0]), "r"(a[1]), "r"(a[2]), "r"(a[3]), "r"(b[0]), "r"(b[1]));
}
__device__ __forceinline__ float sqrt_ap(float x) { float r; asm("sqrt.approx.f32 %0,%1;" : "=f"(r) : "f"(x)); return r; }
__device__ __forceinline__ float rcp_ap(float x)  { float r; asm("rcp.approx.f32 %0,%1;"  : "=f"(r) : "f"(x)); return r; }

// ---------------------------------------------------------------------------
// CTA = 128 threads, 4 warps in 2(n) x 2(m). CTA tile 128x128, warp tile 64x64.
// K = 128 in 4 slices of 32 halfs. Stage = {Ahi 8K, Bhi 8K, Blo 8K} = 24 KB.
// 3-stage cp.async pipeline, one barrier per iteration. 2 CTAs/SM.
// ---------------------------------------------------------------------------
#define STG 24576
#define OB_HI 8192
#define OB_LO 16384

__global__ __launch_bounds__(128, 2)
void simgemm(float* __restrict__ out) {
    extern __shared__ __align__(1024) char sm[];
    uint32_t sb = s2u(sm);
    const int tid = threadIdx.x, lane = tid & 31, w = tid >> 5;
    const int wy = w >> 1, wx = w & 1;      // wy: n-dir (2), wx: m-dir (2)
    const int b = blockIdx.z, bm = blockIdx.x, bn = blockIdx.y;
    const int aRow0 = b * NN + bn * 128;    // src rows (C rows, n)
    const int bRow0 = b * NN + bm * 128;    // tgt rows (C cols, m)

    float acc[4][8][4];
#pragma unroll
    for (int i = 0; i < 4; i++)
#pragma unroll
        for (int j = 0; j < 8; j++)
#pragma unroll
            for (int k = 0; k < 4; k++) acc[i][j][k] = 0.0f;

    // ldmatrix per-thread offsets (within one 8KB tile)
    uint32_t aoff[4][2], boff[4][2];
    {
        int ar = (lane & 7) + ((lane >> 3) & 1) * 8;
        int akg = lane >> 4;
#pragma unroll
        for (int mi = 0; mi < 4; mi++)
#pragma unroll
            for (int kk = 0; kk < 2; kk++)
                aoff[mi][kk] = toff(wy * 64 + mi * 16 + ar, kk * 2 + akg);
        int br = (lane & 7) + (lane >> 4) * 8;
        int bkg = (lane >> 3) & 1;
#pragma unroll
        for (int nip = 0; nip < 4; nip++)
#pragma unroll
            for (int kk = 0; kk < 2; kk++)
                boff[nip][kk] = toff(wx * 64 + nip * 16 + br, kk * 2 + bkg);
    }

    // issue slice s into stage: 3 tiles, 512 granules each, 4/thread/tile
    auto issue = [&](int s, int stage) {
        const __half* gah = g_hiS + (size_t)aRow0 * CC + s * 32;
        const __half* gbh = g_hiT + (size_t)bRow0 * CC + s * 32;
        const __half* gbl = g_loT + (size_t)bRow0 * CC + s * 32;
        uint32_t st = sb + stage * STG;
#pragma unroll
        for (int j = 0; j < 4; j++) {
            int g = tid + j * 128;
            int row = g >> 2, kg = g & 3;
            uint32_t o = toff(row, kg);
            size_t go = (size_t)row * CC + kg * 8;
            cpasync16(st + o,         gah + go);
            cpasync16(st + OB_HI + o, gbh + go);
            cpasync16(st + OB_LO + o, gbl + go);
        }
        asm volatile("cp.async.commit_group;" ::: "memory");
    };

    auto compute = [&](int stage) {
        uint32_t st = sb + stage * STG;
#pragma unroll
        for (int kk = 0; kk < 2; kk++) {
            uint32_t bf[8][2], a[4][4];
            // B hi frags: 4 ldm4 -> 8 n8 tiles
#pragma unroll
            for (int nip = 0; nip < 4; nip++)
                ldm4(bf[nip * 2][0], bf[nip * 2][1], bf[nip * 2 + 1][0],
                     bf[nip * 2 + 1][1], st + OB_HI + boff[nip][kk]);
#pragma unroll
            for (int mi = 0; mi < 4; mi++)
                ldm4(a[mi][0], a[mi][1], a[mi][2], a[mi][3], st + aoff[mi][kk]);
            // hiA x hiB : 64 back-to-back mma
#pragma unroll
            for (int mi = 0; mi < 4; mi++)
#pragma unroll
                for (int ni = 0; ni < 8; ni++)
                    mma16816(acc[mi][ni], a[mi], bf[ni]);
            // reload B frags <- lo (reuse regs), overlaps mma drain
#pragma unroll
            for (int nip = 0; nip < 4; nip++)
                ldm4(bf[nip * 2][0], bf[nip * 2][1], bf[nip * 2 + 1][0],
                     bf[nip * 2 + 1][1], st + OB_LO + boff[nip][kk]);
            // hiA x loB
#pragma unroll
            for (int mi = 0; mi < 4; mi++)
#pragma unroll
                for (int ni = 0; ni < 8; ni++)
                    mma16816(acc[mi][ni], a[mi], bf[ni]);
        }
    };

    // 3-stage pipeline over 4 slices; slice 3 reuses stage 0 (freed at c=1).
    issue(0, 0);
    issue(1, 1);
    issue(2, 2);

    cpwait<2>(); __syncthreads();
    compute(0);

    cpwait<1>(); __syncthreads();
    issue(3, 0);
    compute(1);

    cpwait<1>(); __syncthreads();
    compute(2);

    cpwait<0>(); __syncthreads();
    compute(0);

    // ---- epilogue ----
    const int q = lane >> 2;
    const int mp = (lane & 3) * 2;
#pragma unroll
    for (int mi = 0; mi < 4; mi++) {
        int n0 = bn * 128 + wy * 64 + mi * 16 + q;
        float2 ns0 = g_nS[b * NN + n0];
        float2 ns1 = g_nS[b * NN + n0 + 8];
        float* r0 = out + (((size_t)(b * NN + n0)) * NN) * 2;
        float* r1 = out + (((size_t)(b * NN + n0 + 8)) * NN) * 2;
#pragma unroll
        for (int ni = 0; ni < 8; ni++) {
            int m0 = bm * 128 + wx * 64 + ni * 8 + mp;
            float2 nt0 = g_nT[b * NN + m0];
            float2 nt1 = g_nT[b * NN + m0 + 1];
            const float* cc = acc[mi][ni];

            float cs00 = cc[0] * ns0.y * nt0.y;
            float cs01 = cc[1] * ns0.y * nt1.y;
            float cs10 = cc[2] * ns1.y * nt0.y;
            float cs11 = cc[3] * ns1.y * nt1.y;
            float fd00 = rcp_ap(1.0f + sqrt_ap(fmaxf(ns0.x + nt0.x - 2.0f * cc[0], 0.0f)));
            float fd01 = rcp_ap(1.0f + sqrt_ap(fmaxf(ns0.x + nt1.x - 2.0f * cc[1], 0.0f)));
            float fd10 = rcp_ap(1.0f + sqrt_ap(fmaxf(ns1.x + nt0.x - 2.0f * cc[2], 0.0f)));
            float fd11 = rcp_ap(1.0f + sqrt_ap(fmaxf(ns1.x + nt1.x - 2.0f * cc[3], 0.0f)));

            *(float4*)(r0 + (size_t)m0 * 2) = make_float4(cs00, fd00, cs01, fd01);
            *(float4*)(r1 + (size_t)m0 * 2) = make_float4(cs10, fd10, cs11, fd11);
        }
    }
}

// ---------------------------------------------------------------------------
extern "C" void kernel_launch(void* const* d_in, const int* in_sizes, int n_in,
                              void* d_out, int out_size) {
    const float* src = (const float*)d_in[0];
    const float* tgt = (const float*)d_in[1];
    float* out = (float*)d_out;
    (void)in_sizes; (void)n_in; (void)out_size;

    cudaFuncSetAttribute(simgemm, cudaFuncAttributeMaxDynamicSharedMemorySize,
                         3 * STG);
    prep<<<dim3(1024, 2, 1), 256>>>(src, tgt);
    simgemm<<<dim3(16, 16, 4), 128, 3 * STG>>>(out);
}

// round 12
// speedup vs baseline: 1.5461x; 1.5461x over previous
#include <cuda_runtime.h>
#include <cuda_fp16.h>
#include <cstdint>

// out[b,n,m,0]=cos(src_n,tgt_m), out[b,n,m,1]=1/(1+||src_n-tgt_m||)
// dot via 2-pass split-fp16 mma.sync: hiA*hiB + hiA*loB, fp32 accumulate.

#define NN 2048
#define CC 128
#define ROWSZ (4 * NN)

__device__ __half g_hiS[ROWSZ * CC];
__device__ __half g_hiT[ROWSZ * CC];
__device__ __half g_loT[ROWSZ * CC];
__device__ float2 g_nS[ROWSZ];   // {|s|^2, 1/max(|s|,eps)}
__device__ float2 g_nT[ROWSZ];

// ---------------------------------------------------------------------------
// prep: fp32 -> fp16 hi (+ lo for tgt only) + fused row norms. Warp per row.
// ---------------------------------------------------------------------------
__global__ void prep(const float* __restrict__ S, const float* __restrict__ T) {
    int gw = (blockIdx.x * blockDim.x + threadIdx.x) >> 5;
    int lane = threadIdx.x & 31;
    if (gw >= ROWSZ) return;
    bool ist = (blockIdx.y != 0);
    const float* p = (ist ? T : S) + (size_t)gw * CC + lane * 4;
    float4 v = *(const float4*)p;
    float sq = v.x * v.x + v.y * v.y + v.z * v.z + v.w * v.w;
#pragma unroll
    for (int o = 16; o; o >>= 1) sq += __shfl_xor_sync(0xffffffffu, sq, o);

    __half2 h01 = __floats2half2_rn(v.x, v.y);
    __half2 h23 = __floats2half2_rn(v.z, v.w);

    size_t off = (size_t)gw * CC + lane * 4;
    if (ist) {
        float2 f01 = __half22float2(h01);
        float2 f23 = __half22float2(h23);
        __half2 l01 = __floats2half2_rn(v.x - f01.x, v.y - f01.y);
        __half2 l23 = __floats2half2_rn(v.z - f23.x, v.w - f23.y);
        *(uint2*)(g_hiT + off) = make_uint2(*(uint32_t*)&h01, *(uint32_t*)&h23);
        *(uint2*)(g_loT + off) = make_uint2(*(uint32_t*)&l01, *(uint32_t*)&l23);
    } else {
        *(uint2*)(g_hiS + off) = make_uint2(*(uint32_t*)&h01, *(uint32_t*)&h23);
    }
    if (lane == 0) {
        float2 nv;
        nv.x = sq;
        nv.y = 1.0f / fmaxf(sqrtf(sq), 1e-12f);
        (ist ? g_nT : g_nS)[gw] = nv;
    }
}

// ---------------------------------------------------------------------------
__device__ __forceinline__ uint32_t s2u(const void* p) {
    uint32_t a;
    asm("{ .reg .u64 t; cvta.to.shared.u64 t, %1; cvt.u32.u64 %0, t; }" : "=r"(a) : "l"(p));
    return a;
}
// Tile = 128 rows x 64 halfs (128 B/row), classic SW128 8x8 swizzle:
// offset = row*128 + ((kg ^ (row&7)) * 16), kg = 16B granule 0..7.
// Conflict-free for cp.async stores (4 rows x 8 kg per warp) and ldmatrix.
// Property: addr(kg+4) = addr(kg) ^ 64 for kg<4 (bit2 of kg clear).
__device__ __forceinline__ uint32_t toff(int row, int kg) {
    return (uint32_t)((row << 7) + (((kg ^ (row & 7))) << 4));
}
__device__ __forceinline__ void cpasync16(uint32_t s, const void* g) {
    asm volatile("cp.async.cg.shared.global [%0], [%1], 16;" :: "r"(s), "l"(g) : "memory");
}
template <int N>
__device__ __forceinline__ void cpwait() {
    asm volatile("cp.async.wait_group %0;" :: "n"(N) : "memory");
}
__device__ __forceinline__ void ldm4(uint32_t& r0, uint32_t& r1, uint32_t& r2,
                                     uint32_t& r3, uint32_t a) {
    asm volatile("ldmatrix.sync.aligned.m8n8.x4.shared.b16 {%0,%1,%2,%3}, [%4];"
                 : "=r"(r0), "=r"(r1), "=r"(r2), "=r"(r3) : "r"(a));
}
__device__ __forceinline__ void mma16816(float* c, const uint32_t* a, const uint32_t* b) {
    asm volatile(
        "mma.sync.aligned.m16n8k16.row.col.f32.f16.f16.f32 "
        "{%0,%1,%2,%3}, {%4,%5,%6,%7}, {%8,%9}, {%0,%1,%2,%3};"
        : "+f"(c[0]), "+f"(c[1]), "+f"(c[2]), "+f"(c[3])
        : "r"(a[0]), "r"(a[1]), "r"(a[2]), "r"(a[3]), "r"(b[0]), "r"(b[1]));
}
__device__ __forceinline__ float sqrt_ap(float x) { float r; asm("sqrt.approx.f32 %0,%1;" : "=f"(r) : "f"(x)); return r; }
__device__ __forceinline__ float rcp_ap(float x)  { float r; asm("rcp.approx.f32 %0,%1;"  : "=f"(r) : "f"(x)); return r; }

// ---------------------------------------------------------------------------
// CTA tile 128(n) x 128(m), 8 warps 2(n) x 4(m), warp tile 64x32 (R9 shape).
// K = 128 in 2 slices of 64 halfs. Stage = {Ahi 16K, Bhi 16K, Blo 16K} = 48 KB.
// 2-stage cp.async pipeline: 2 waits + 2 barriers per tile. 2 CTAs/SM.
// ---------------------------------------------------------------------------
#define STG 49152
#define OB_HI 16384
#define OB_LO 32768

__global__ __launch_bounds__(256, 2)
void simgemm(float* __restrict__ out) {
    extern __shared__ __align__(1024) char sm[];
    uint32_t sb = s2u(sm);
    const int tid = threadIdx.x, lane = tid & 31, w = tid >> 5;
    const int wm = w & 1, wn = w >> 1;      // wm: n-dir (2), wn: m-dir (4)
    const int b = blockIdx.z, bm = blockIdx.x, bn = blockIdx.y;
    const int aRow0 = b * NN + bn * 128;    // src rows (C rows, n)
    const int bRow0 = b * NN + bm * 128;    // tgt rows (C cols, m)

    float acc[4][4][4];
#pragma unroll
    for (int i = 0; i < 4; i++)
#pragma unroll
        for (int j = 0; j < 4; j++)
#pragma unroll
            for (int k = 0; k < 4; k++) acc[i][j][k] = 0.0f;

    // ldmatrix offsets for kk=0,1 only; kk=2,3 derived via ^64.
    uint32_t aoff[4][2], boff[2][2];
    {
        int ar = (lane & 7) + ((lane >> 3) & 1) * 8;
        int akg = lane >> 4;
#pragma unroll
        for (int mi = 0; mi < 4; mi++)
#pragma unroll
            for (int kk = 0; kk < 2; kk++)
                aoff[mi][kk] = toff(wm * 64 + mi * 16 + ar, kk * 2 + akg);
        int br = (lane & 7) + (lane >> 4) * 8;
        int bkg = (lane >> 3) & 1;
#pragma unroll
        for (int nip = 0; nip < 2; nip++)
#pragma unroll
            for (int kk = 0; kk < 2; kk++)
                boff[nip][kk] = toff(wn * 32 + nip * 16 + br, kk * 2 + bkg);
    }

    // issue 64-half K-slice s into stage: 3 tiles x 1024 granules, 12/thread
    auto issue = [&](int s, int stage) {
        const __half* gah = g_hiS + (size_t)aRow0 * CC + s * 64;
        const __half* gbh = g_hiT + (size_t)bRow0 * CC + s * 64;
        const __half* gbl = g_loT + (size_t)bRow0 * CC + s * 64;
        uint32_t st = sb + stage * STG;
#pragma unroll
        for (int j = 0; j < 4; j++) {
            int g = tid + j * 256;
            int row = g >> 3, kg = g & 7;
            uint32_t o = toff(row, kg);
            size_t go = (size_t)row * CC + kg * 8;
            cpasync16(st + o,         gah + go);
            cpasync16(st + OB_HI + o, gbh + go);
            cpasync16(st + OB_LO + o, gbl + go);
        }
        asm volatile("cp.async.commit_group;" ::: "memory");
    };

    auto compute = [&](int stage) {
        uint32_t st = sb + stage * STG;
#pragma unroll
        for (int kk = 0; kk < 4; kk++) {
            const uint32_t x = (kk & 2) ? 64u : 0u;
            const int k2 = kk & 1;
            uint32_t bf[4][2], a[4][4];
            // B hi frags (32 m-cols = 2 ldm4)
#pragma unroll
            for (int nip = 0; nip < 2; nip++)
                ldm4(bf[nip * 2][0], bf[nip * 2][1], bf[nip * 2 + 1][0],
                     bf[nip * 2 + 1][1], st + OB_HI + (boff[nip][k2] ^ x));
#pragma unroll
            for (int mi = 0; mi < 4; mi++)
                ldm4(a[mi][0], a[mi][1], a[mi][2], a[mi][3],
                     st + (aoff[mi][k2] ^ x));
            // hiA x hiB
#pragma unroll
            for (int mi = 0; mi < 4; mi++)
#pragma unroll
                for (int ni = 0; ni < 4; ni++)
                    mma16816(acc[mi][ni], a[mi], bf[ni]);
            // reload bf <- lo (reuse regs), overlaps mma drain
#pragma unroll
            for (int nip = 0; nip < 2; nip++)
                ldm4(bf[nip * 2][0], bf[nip * 2][1], bf[nip * 2 + 1][0],
                     bf[nip * 2 + 1][1], st + OB_LO + (boff[nip][k2] ^ x));
            // hiA x loB
#pragma unroll
            for (int mi = 0; mi < 4; mi++)
#pragma unroll
                for (int ni = 0; ni < 4; ni++)
                    mma16816(acc[mi][ni], a[mi], bf[ni]);
        }
    };

    // 2-stage pipeline over 2 slices
    issue(0, 0);
    issue(1, 1);

    cpwait<1>(); __syncthreads();
    compute(0);

    cpwait<0>(); __syncthreads();
    compute(1);

    // ---- epilogue ----
    const int q = lane >> 2;
    const int mp = (lane & 3) * 2;
#pragma unroll
    for (int mi = 0; mi < 4; mi++) {
        int n0 = bn * 128 + wm * 64 + mi * 16 + q;
        float2 ns0 = g_nS[b * NN + n0];
        float2 ns1 = g_nS[b * NN + n0 + 8];
        float* r0 = out + (((size_t)(b * NN + n0)) * NN) * 2;
        float* r1 = out + (((size_t)(b * NN + n0 + 8)) * NN) * 2;
#pragma unroll
        for (int ni = 0; ni < 4; ni++) {
            int m0 = bm * 128 + wn * 32 + ni * 8 + mp;
            float2 nt0 = g_nT[b * NN + m0];
            float2 nt1 = g_nT[b * NN + m0 + 1];
            const float* cc = acc[mi][ni];

            float cs00 = cc[0] * ns0.y * nt0.y;
            float cs01 = cc[1] * ns0.y * nt1.y;
            float cs10 = cc[2] * ns1.y * nt0.y;
            float cs11 = cc[3] * ns1.y * nt1.y;
            float fd00 = rcp_ap(1.0f + sqrt_ap(fmaxf(ns0.x + nt0.x - 2.0f * cc[0], 0.0f)));
            float fd01 = rcp_ap(1.0f + sqrt_ap(fmaxf(ns0.x + nt1.x - 2.0f * cc[1], 0.0f)));
            float fd10 = rcp_ap(1.0f + sqrt_ap(fmaxf(ns1.x + nt0.x - 2.0f * cc[2], 0.0f)));
            float fd11 = rcp_ap(1.0f + sqrt_ap(fmaxf(ns1.x + nt1.x - 2.0f * cc[3], 0.0f)));

            *(float4*)(r0 + (size_t)m0 * 2) = make_float4(cs00, fd00, cs01, fd01);
            *(float4*)(r1 + (size_t)m0 * 2) = make_float4(cs10, fd10, cs11, fd11);
        }
    }
}

// ---------------------------------------------------------------------------
extern "C" void kernel_launch(void* const* d_in, const int* in_sizes, int n_in,
                              void* d_out, int out_size) {
    const float* src = (const float*)d_in[0];
    const float* tgt = (const float*)d_in[1];
    float* out = (float*)d_out;
    (void)in_sizes; (void)n_in; (void)out_size;

    cudaFuncSetAttribute(simgemm, cudaFuncAttributeMaxDynamicSharedMemorySize,
                         2 * STG);
    prep<<<dim3(1024, 2, 1), 256>>>(src, tgt);
    simgemm<<<dim3(16, 16, 4), 256, 2 * STG>>>(out);
}